// round 15
// baseline (speedup 1.0000x reference)
#include <cuda_runtime.h>
#include <cstdint>

// Problem constants
#define NTOK   8192        // B*S = 4*2048
#define DMODEL 1024
#define NEXP   8
#define HID    2048
#define TOPK   2
#define TM     128
#define TN     128
#define TKK    16
#define MAXR   (NTOK*TOPK + NEXP*TM)   // 17408
#define NROWT  (MAXR/TM)               // 136 row tiles
#define GRP    24                      // 16 G1 tiles + 8 G2 tiles per row group
#define TOT_TILES (NROWT*GRP)          // 3264
#define OUT_ELEMS (NTOK*DMODEL)
#define PERSIST_CTAS 304               // 152 SM * 2

// ---------------- device scratch (no allocation allowed) ----------------
__device__ int   g_tope[NTOK*2];
__device__ float g_topp[NTOK*2];
__device__ int   g_perm_tok[MAXR];
__device__ float g_rowp[MAXR];          // per permuted row: gating prob
__device__ int   g_fcount[NEXP];
__device__ int   g_scount[NEXP];
__device__ int   g_off[NEXP+1];
__device__ int   g_cursor[NEXP];
__device__ float g_blockP[(NTOK/8)*NEXP];
__device__ int   g_tile_ctr;
__device__ int   g_ready[NROWT];
__device__ float g_hidden[(size_t)MAXR*HID];

// ---------------- prep: zero the small control state (1 block) ----------------
__global__ void prep_kernel() {
    int i = threadIdx.x;
    if (i < NEXP) { g_fcount[i] = 0; g_scount[i] = 0; }
    if (i < NROWT) g_ready[i] = 0;
    if (i == 0) g_tile_ctr = 0;
}

// ---------------- router ----------------
__global__ void __launch_bounds__(256) router_kernel(const float* __restrict__ x,
                                                     const float* __restrict__ gate_w) {
    __shared__ float sg[NEXP * DMODEL];
    __shared__ float warpP[8][NEXP];
    int tid = threadIdx.x;
    for (int i = tid; i < NEXP * DMODEL; i += 256) sg[i] = gate_w[i];
    __syncthreads();

    int warp = tid >> 5, lane = tid & 31;
    int t = blockIdx.x * 8 + warp;
    const float* xr = x + (size_t)t * DMODEL;

    float acc[NEXP];
#pragma unroll
    for (int e = 0; e < NEXP; e++) acc[e] = 0.f;
    for (int j = 0; j < DMODEL / 32; j++) {
        float v = xr[j * 32 + lane];
#pragma unroll
        for (int e = 0; e < NEXP; e++) acc[e] += v * sg[e * DMODEL + j * 32 + lane];
    }
#pragma unroll
    for (int e = 0; e < NEXP; e++)
#pragma unroll
        for (int o = 16; o > 0; o >>= 1) acc[e] += __shfl_xor_sync(0xffffffffu, acc[e], o);

    if (lane == 0) {
        float m = acc[0];
#pragma unroll
        for (int e = 1; e < NEXP; e++) m = fmaxf(m, acc[e]);
        float p[NEXP], s = 0.f;
#pragma unroll
        for (int e = 0; e < NEXP; e++) { p[e] = __expf(acc[e] - m); s += p[e]; }
        float inv = 1.f / s;
#pragma unroll
        for (int e = 0; e < NEXP; e++) p[e] *= inv;
        int i1 = 0;
#pragma unroll
        for (int e = 1; e < NEXP; e++) if (p[e] > p[i1]) i1 = e;
        int i2 = (i1 == 0) ? 1 : 0;
#pragma unroll
        for (int e = 0; e < NEXP; e++) if (e != i1 && p[e] > p[i2]) i2 = e;
        float s2 = p[i1] + p[i2];
        g_tope[t * 2 + 0] = i1;  g_topp[t * 2 + 0] = p[i1] / s2;
        g_tope[t * 2 + 1] = i2;  g_topp[t * 2 + 1] = p[i2] / s2;
        atomicAdd(&g_fcount[i1], 1);
        atomicAdd(&g_scount[i1], 1);
        atomicAdd(&g_scount[i2], 1);
#pragma unroll
        for (int e = 0; e < NEXP; e++) warpP[warp][e] = p[e];
    }
    __syncthreads();
    if (tid < NEXP) {
        float s = 0.f;
#pragma unroll
        for (int w = 0; w < 8; w++) s += warpP[w][tid];
        g_blockP[blockIdx.x * NEXP + tid] = s;
    }
}

// ---------------- offsets + padding fill ----------------
__global__ void __launch_bounds__(256) offsets_kernel() {
    __shared__ int soff[NEXP + 1];
    __shared__ int scnt[NEXP];
    if (threadIdx.x == 0) {
        int o = 0;
        for (int e = 0; e < NEXP; e++) {
            g_off[e] = o; soff[e] = o;
            g_cursor[e] = o;
            int c = g_scount[e];
            scnt[e] = c;
            o += ((c + TM - 1) / TM) * TM;
        }
        g_off[NEXP] = o; soff[NEXP] = o;
    }
    __syncthreads();
    // fill padding rows with -1
    for (int e = 0; e < NEXP; e++) {
        int start = soff[e] + scnt[e], end = soff[e + 1];
        for (int i = start + threadIdx.x; i < end; i += 256) g_perm_tok[i] = -1;
    }
}

// ---------------- scatter ----------------
__global__ void scatter_kernel() {
    int t = blockIdx.x * blockDim.x + threadIdx.x;
    if (t >= NTOK) return;
#pragma unroll
    for (int k = 0; k < 2; k++) {
        int e = g_tope[t * 2 + k];
        int pos = atomicAdd(&g_cursor[e], 1);
        g_perm_tok[pos] = t;
        g_rowp[pos] = g_topp[t * 2 + k];
    }
}

// ---------------- helpers ----------------
__device__ __forceinline__ void ffma2(unsigned long long& c, unsigned long long a,
                                      unsigned long long b) {
    asm("fma.rn.f32x2 %0, %1, %2, %0;" : "+l"(c) : "l"(a), "l"(b));
}
__device__ __forceinline__ int ld_acquire(const int* p) {
    int v;
    asm volatile("ld.acquire.gpu.s32 %0, [%1];" : "=r"(v) : "l"(p) : "memory");
    return v;
}
__device__ __forceinline__ void red_add(float* p, float v) {
    asm volatile("red.global.add.f32 [%0], %1;" :: "l"(p), "f"(v) : "memory");
}

// ---------------- one 128x128 GEMM tile (R10 proven mapping + loop order) ----------------
// COMBINE=false: store to Out (optionally relu). COMBINE=true: atomic-scatter to out.
template<bool GATHER, bool RELU, bool COMBINE, int KD, int NO>
__device__ __forceinline__ void gemm_tile(
    const float* __restrict__ Asrc, const float* __restrict__ W,
    float* __restrict__ Out, int row0, int bn0,
    float (*As)[TKK][2 * TM], float (*Bs)[TKK][TN])
{
    int e = 0;
#pragma unroll
    for (int q = 1; q < NEXP; q++) if (row0 >= g_off[q]) e = q;
    const float* B = W + (size_t)e * KD * NO;
    int tid = threadIdx.x;

    int ar = tid >> 1, ak = (tid & 1) * 8;
    int bk = tid >> 4, btx = tid & 15;
    int tx = tid & 15, ty = tid >> 4;
    int tokA = 0;
    const float* Arow;
    if (GATHER) {
        tokA = g_perm_tok[row0 + ar];
        Arow = (tokA >= 0) ? (Asrc + (size_t)tokA * KD + ak) : Asrc;
    } else {
        Arow = Asrc + (size_t)(row0 + ar) * KD + ak;
    }
    const float* Brow = B + (size_t)bk * NO + bn0 + 4 * btx;

    unsigned long long acc[8][4];
#pragma unroll
    for (int i = 0; i < 8; i++)
#pragma unroll
        for (int j = 0; j < 4; j++) acc[i][j] = 0ull;

    // prologue: tile 0
    {
        float4 a0 = make_float4(0.f, 0.f, 0.f, 0.f), a1 = a0;
        if (!GATHER || tokA >= 0) { a0 = *(const float4*)(Arow); a1 = *(const float4*)(Arow + 4); }
#pragma unroll
        for (int j = 0; j < 4; j++) {
            float v0 = (&a0.x)[j], v1 = (&a1.x)[j];
            *(float2*)&As[0][ak + j][2 * ar] = make_float2(v0, v0);
            *(float2*)&As[0][ak + 4 + j][2 * ar] = make_float2(v1, v1);
        }
        *(float4*)&Bs[0][bk][4 * btx] = *(const float4*)Brow;
        *(float4*)&Bs[0][bk][64 + 4 * btx] = *(const float4*)(Brow + 64);
    }
    __syncthreads();

    const int nk = KD / TKK;
    for (int kt = 0; kt < nk; kt++) {
        int buf = kt & 1;
        float4 a0n, a1n, b0n, b1n;
        bool more = (kt + 1 < nk);
        if (more) {
            a0n = make_float4(0.f, 0.f, 0.f, 0.f); a1n = a0n;
            if (!GATHER || tokA >= 0) {
                a0n = *(const float4*)(Arow + (kt + 1) * TKK);
                a1n = *(const float4*)(Arow + (kt + 1) * TKK + 4);
            }
            const float* bp = Brow + (size_t)(kt + 1) * TKK * NO;
            b0n = *(const float4*)bp;
            b1n = *(const float4*)(bp + 64);
        }
#pragma unroll
        for (int kk = 0; kk < TKK; kk++) {
            unsigned long long a8[8], b4[4];
#pragma unroll
            for (int i = 0; i < 4; i++) {
                ulonglong2 t2 = *(const ulonglong2*)&As[buf][kk][2 * (ty * 8 + 2 * i)];
                a8[2 * i] = t2.x;  a8[2 * i + 1] = t2.y;
            }
            {
                ulonglong2 t0 = *(const ulonglong2*)&Bs[buf][kk][4 * tx];
                ulonglong2 t1 = *(const ulonglong2*)&Bs[buf][kk][64 + 4 * tx];
                b4[0] = t0.x;  b4[1] = t0.y;  b4[2] = t1.x;  b4[3] = t1.y;
            }
            // i-outer/j-inner: measured-best schedule (R9/R10)
#pragma unroll
            for (int i = 0; i < 8; i++)
#pragma unroll
                for (int j = 0; j < 4; j++) ffma2(acc[i][j], a8[i], b4[j]);
        }
        if (more) {
            int nb = buf ^ 1;
#pragma unroll
            for (int j = 0; j < 4; j++) {
                float v0 = (&a0n.x)[j], v1 = (&a1n.x)[j];
                *(float2*)&As[nb][ak + j][2 * ar] = make_float2(v0, v0);
                *(float2*)&As[nb][ak + 4 + j][2 * ar] = make_float2(v1, v1);
            }
            *(float4*)&Bs[nb][bk][4 * btx] = b0n;
            *(float4*)&Bs[nb][bk][64 + 4 * btx] = b1n;
            __syncthreads();
        }
    }

    // epilogue
#pragma unroll
    for (int i = 0; i < 8; i++) {
        int row = row0 + ty * 8 + i;
        float2 p0 = *(float2*)&acc[i][0];
        float2 p1 = *(float2*)&acc[i][1];
        float2 p2 = *(float2*)&acc[i][2];
        float2 p3 = *(float2*)&acc[i][3];
        if (COMBINE) {
            int tok = g_perm_tok[row];
            if (tok < 0) continue;
            float p = g_rowp[row];
            float* dst = Out + (size_t)tok * NO + bn0;
            red_add(dst + 4 * tx + 0, p * p0.x);
            red_add(dst + 4 * tx + 1, p * p0.y);
            red_add(dst + 4 * tx + 2, p * p1.x);
            red_add(dst + 4 * tx + 3, p * p1.y);
            red_add(dst + 64 + 4 * tx + 0, p * p2.x);
            red_add(dst + 64 + 4 * tx + 1, p * p2.y);
            red_add(dst + 64 + 4 * tx + 2, p * p3.x);
            red_add(dst + 64 + 4 * tx + 3, p * p3.y);
        } else {
            float* dst = Out + (size_t)row * NO + bn0;
            float4 v0, v1;
            if (RELU) {
                v0 = make_float4(fmaxf(p0.x, 0.f), fmaxf(p0.y, 0.f),
                                 fmaxf(p1.x, 0.f), fmaxf(p1.y, 0.f));
                v1 = make_float4(fmaxf(p2.x, 0.f), fmaxf(p2.y, 0.f),
                                 fmaxf(p3.x, 0.f), fmaxf(p3.y, 0.f));
            } else {
                v0 = make_float4(p0.x, p0.y, p1.x, p1.y);
                v1 = make_float4(p2.x, p2.y, p3.x, p3.y);
            }
            *(float4*)(dst + 4 * tx) = v0;
            *(float4*)(dst + 64 + 4 * tx) = v1;
        }
    }
}

// ---------------- fused persistent GEMM1+GEMM2(+combine), interleaved row-group queue ----------------
// Queue order: for each row-tile y: 16 GEMM1 tiles, then 8 GEMM2 tiles.
// Keeps g_hidden row-tiles L2-resident between producer and consumer.
__global__ void __launch_bounds__(256, 2) moe_fused_gemm(
    const float* __restrict__ x, const float* __restrict__ w1,
    const float* __restrict__ w2, float* __restrict__ out)
{
    __shared__ float As[2][TKK][2 * TM];   // 32 KB
    __shared__ float Bs[2][TKK][TN];       // 16 KB
    __shared__ int s_t;
    int tid = threadIdx.x;
    int rows_used = g_off[NEXP];

    while (true) {
        __syncthreads();                       // smem reuse + s_t protection
        if (tid == 0) s_t = atomicAdd(&g_tile_ctr, 1);
        __syncthreads();
        int t = s_t;
        if (t >= TOT_TILES) return;

        int y = t / GRP, r = t % GRP;
        int row0 = y * TM;
        if (r < 16) {
            // GEMM1 tile: hidden = relu(gather(x) @ w1[e])
            if (row0 < rows_used)
                gemm_tile<true, true, false, DMODEL, HID>(x, w1, g_hidden, row0, r * TN, As, Bs);
            __threadfence();
            __syncthreads();
            if (tid == 0) atomicAdd(&g_ready[y], 1);
        } else {
            // GEMM2 tile: out += p * (hidden @ w2[e])
            if (row0 >= rows_used) continue;
            if (tid == 0) {
                while (ld_acquire(&g_ready[y]) < 16) __nanosleep(64);
            }
            __syncthreads();
            gemm_tile<false, false, true, HID, DMODEL>(g_hidden, w2, out, row0, (r - 16) * TN, As, Bs);
        }
    }
}

// ---------------- aux loss ----------------
__global__ void aux_kernel(float* __restrict__ out, int out_size) {
    __shared__ float P[NEXP];
    int e = threadIdx.x;
    if (e < NEXP) {
        float s = 0.f;
        for (int b = 0; b < NTOK / 8; b++) s += g_blockP[b * NEXP + e];
        P[e] = s * (1.0f / NTOK);
    }
    __syncthreads();
    if (threadIdx.x == 0 && out_size > OUT_ELEMS) {
        float aux = 0.f;
        for (int q = 0; q < NEXP; q++)
            aux += ((float)g_fcount[q] * (1.0f / NTOK)) * P[q];
        aux *= 0.01f * NEXP;
        out[OUT_ELEMS] = aux;
    }
}

// ---------------- launch ----------------
extern "C" void kernel_launch(void* const* d_in, const int* in_sizes, int n_in,
                              void* d_out, int out_size) {
    const float* x      = (const float*)d_in[0];
    const float* gate_w = (const float*)d_in[1];
    const float* w1     = (const float*)d_in[2];
    const float* w2     = (const float*)d_in[3];
    float* out = (float*)d_out;

    cudaMemsetAsync(out, 0, (size_t)out_size * sizeof(float));
    prep_kernel<<<1, 256>>>();
    router_kernel<<<NTOK / 8, 256>>>(x, gate_w);
    offsets_kernel<<<1, 256>>>();
    scatter_kernel<<<(NTOK + 255) / 256, 256>>>();

    moe_fused_gemm<<<PERSIST_CTAS, 256>>>(x, w1, w2, out);

    aux_kernel<<<1, 32>>>(out, out_size);
}

// round 16
// speedup vs baseline: 1.2127x; 1.2127x over previous
#include <cuda_runtime.h>
#include <cstdint>

// Problem constants
#define NTOK   8192        // B*S = 4*2048
#define DMODEL 1024
#define NEXP   8
#define HID    2048
#define TOPK   2
#define TM     128
#define TN     128
#define TKK    16
#define MAXR   (NTOK*TOPK + NEXP*TM)   // 17408
#define NROWT  (MAXR/TM)               // 136 row tiles
#define GRP    24                      // 16 G1 slots + 8 G2 slots per virtual group
#define DELAY  24                      // G2 trails G1 by 24 row groups (576 tile slots)
#define NGRP   (NROWT + DELAY)         // 160 virtual groups
#define TOT_TILES (NGRP*GRP)           // 3840 slots (some empty)
#define OUT_ELEMS (NTOK*DMODEL)
#define PERSIST_CTAS 304               // 152 SM * 2

// ---------------- device scratch (no allocation allowed) ----------------
__device__ int   g_tope[NTOK*2];
__device__ float g_topp[NTOK*2];
__device__ int   g_perm_tok[MAXR];
__device__ float g_rowp[MAXR];          // per permuted row: gating prob
__device__ int   g_fcount[NEXP];
__device__ int   g_scount[NEXP];
__device__ int   g_off[NEXP+1];
__device__ int   g_cursor[NEXP];
__device__ float g_blockP[(NTOK/8)*NEXP];
__device__ int   g_tile_ctr;
__device__ int   g_ready[NROWT];
__device__ float g_hidden[(size_t)MAXR*HID];

// ---------------- prep: zero the small control state (1 block) ----------------
__global__ void prep_kernel() {
    int i = threadIdx.x;
    if (i < NEXP) { g_fcount[i] = 0; g_scount[i] = 0; }
    if (i < NROWT) g_ready[i] = 0;
    if (i == 0) g_tile_ctr = 0;
}

// ---------------- router ----------------
__global__ void __launch_bounds__(256) router_kernel(const float* __restrict__ x,
                                                     const float* __restrict__ gate_w) {
    __shared__ float sg[NEXP * DMODEL];
    __shared__ float warpP[8][NEXP];
    int tid = threadIdx.x;
    for (int i = tid; i < NEXP * DMODEL; i += 256) sg[i] = gate_w[i];
    __syncthreads();

    int warp = tid >> 5, lane = tid & 31;
    int t = blockIdx.x * 8 + warp;
    const float* xr = x + (size_t)t * DMODEL;

    float acc[NEXP];
#pragma unroll
    for (int e = 0; e < NEXP; e++) acc[e] = 0.f;
    for (int j = 0; j < DMODEL / 32; j++) {
        float v = xr[j * 32 + lane];
#pragma unroll
        for (int e = 0; e < NEXP; e++) acc[e] += v * sg[e * DMODEL + j * 32 + lane];
    }
#pragma unroll
    for (int e = 0; e < NEXP; e++)
#pragma unroll
        for (int o = 16; o > 0; o >>= 1) acc[e] += __shfl_xor_sync(0xffffffffu, acc[e], o);

    if (lane == 0) {
        float m = acc[0];
#pragma unroll
        for (int e = 1; e < NEXP; e++) m = fmaxf(m, acc[e]);
        float p[NEXP], s = 0.f;
#pragma unroll
        for (int e = 0; e < NEXP; e++) { p[e] = __expf(acc[e] - m); s += p[e]; }
        float inv = 1.f / s;
#pragma unroll
        for (int e = 0; e < NEXP; e++) p[e] *= inv;
        int i1 = 0;
#pragma unroll
        for (int e = 1; e < NEXP; e++) if (p[e] > p[i1]) i1 = e;
        int i2 = (i1 == 0) ? 1 : 0;
#pragma unroll
        for (int e = 0; e < NEXP; e++) if (e != i1 && p[e] > p[i2]) i2 = e;
        float s2 = p[i1] + p[i2];
        g_tope[t * 2 + 0] = i1;  g_topp[t * 2 + 0] = p[i1] / s2;
        g_tope[t * 2 + 1] = i2;  g_topp[t * 2 + 1] = p[i2] / s2;
        atomicAdd(&g_fcount[i1], 1);
        atomicAdd(&g_scount[i1], 1);
        atomicAdd(&g_scount[i2], 1);
#pragma unroll
        for (int e = 0; e < NEXP; e++) warpP[warp][e] = p[e];
    }
    __syncthreads();
    if (tid < NEXP) {
        float s = 0.f;
#pragma unroll
        for (int w = 0; w < 8; w++) s += warpP[w][tid];
        g_blockP[blockIdx.x * NEXP + tid] = s;
    }
}

// ---------------- offsets + padding fill ----------------
__global__ void __launch_bounds__(256) offsets_kernel() {
    __shared__ int soff[NEXP + 1];
    __shared__ int scnt[NEXP];
    if (threadIdx.x == 0) {
        int o = 0;
        for (int e = 0; e < NEXP; e++) {
            g_off[e] = o; soff[e] = o;
            g_cursor[e] = o;
            int c = g_scount[e];
            scnt[e] = c;
            o += ((c + TM - 1) / TM) * TM;
        }
        g_off[NEXP] = o; soff[NEXP] = o;
    }
    __syncthreads();
    // fill padding rows with -1
    for (int e = 0; e < NEXP; e++) {
        int start = soff[e] + scnt[e], end = soff[e + 1];
        for (int i = start + threadIdx.x; i < end; i += 256) g_perm_tok[i] = -1;
    }
}

// ---------------- scatter ----------------
__global__ void scatter_kernel() {
    int t = blockIdx.x * blockDim.x + threadIdx.x;
    if (t >= NTOK) return;
#pragma unroll
    for (int k = 0; k < 2; k++) {
        int e = g_tope[t * 2 + k];
        int pos = atomicAdd(&g_cursor[e], 1);
        g_perm_tok[pos] = t;
        g_rowp[pos] = g_topp[t * 2 + k];
    }
}

// ---------------- helpers ----------------
__device__ __forceinline__ void ffma2(unsigned long long& c, unsigned long long a,
                                      unsigned long long b) {
    asm("fma.rn.f32x2 %0, %1, %2, %0;" : "+l"(c) : "l"(a), "l"(b));
}
__device__ __forceinline__ int ld_acquire(const int* p) {
    int v;
    asm volatile("ld.acquire.gpu.s32 %0, [%1];" : "=r"(v) : "l"(p) : "memory");
    return v;
}
__device__ __forceinline__ void red_add(float* p, float v) {
    asm volatile("red.global.add.f32 [%0], %1;" :: "l"(p), "f"(v) : "memory");
}

// ---------------- one 128x128 GEMM tile (R10 proven mapping + loop order) ----------------
// COMBINE=false: store to Out (optionally relu). COMBINE=true: atomic-scatter to out.
template<bool GATHER, bool RELU, bool COMBINE, int KD, int NO>
__device__ __forceinline__ void gemm_tile(
    const float* __restrict__ Asrc, const float* __restrict__ W,
    float* __restrict__ Out, int row0, int bn0,
    float (*As)[TKK][2 * TM], float (*Bs)[TKK][TN])
{
    int e = 0;
#pragma unroll
    for (int q = 1; q < NEXP; q++) if (row0 >= g_off[q]) e = q;
    const float* B = W + (size_t)e * KD * NO;
    int tid = threadIdx.x;

    int ar = tid >> 1, ak = (tid & 1) * 8;
    int bk = tid >> 4, btx = tid & 15;
    int tx = tid & 15, ty = tid >> 4;
    int tokA = 0;
    const float* Arow;
    if (GATHER) {
        tokA = g_perm_tok[row0 + ar];
        Arow = (tokA >= 0) ? (Asrc + (size_t)tokA * KD + ak) : Asrc;
    } else {
        Arow = Asrc + (size_t)(row0 + ar) * KD + ak;
    }
    const float* Brow = B + (size_t)bk * NO + bn0 + 4 * btx;

    unsigned long long acc[8][4];
#pragma unroll
    for (int i = 0; i < 8; i++)
#pragma unroll
        for (int j = 0; j < 4; j++) acc[i][j] = 0ull;

    // prologue: tile 0
    {
        float4 a0 = make_float4(0.f, 0.f, 0.f, 0.f), a1 = a0;
        if (!GATHER || tokA >= 0) { a0 = *(const float4*)(Arow); a1 = *(const float4*)(Arow + 4); }
#pragma unroll
        for (int j = 0; j < 4; j++) {
            float v0 = (&a0.x)[j], v1 = (&a1.x)[j];
            *(float2*)&As[0][ak + j][2 * ar] = make_float2(v0, v0);
            *(float2*)&As[0][ak + 4 + j][2 * ar] = make_float2(v1, v1);
        }
        *(float4*)&Bs[0][bk][4 * btx] = *(const float4*)Brow;
        *(float4*)&Bs[0][bk][64 + 4 * btx] = *(const float4*)(Brow + 64);
    }
    __syncthreads();

    const int nk = KD / TKK;
    for (int kt = 0; kt < nk; kt++) {
        int buf = kt & 1;
        float4 a0n, a1n, b0n, b1n;
        bool more = (kt + 1 < nk);
        if (more) {
            a0n = make_float4(0.f, 0.f, 0.f, 0.f); a1n = a0n;
            if (!GATHER || tokA >= 0) {
                a0n = *(const float4*)(Arow + (kt + 1) * TKK);
                a1n = *(const float4*)(Arow + (kt + 1) * TKK + 4);
            }
            const float* bp = Brow + (size_t)(kt + 1) * TKK * NO;
            b0n = *(const float4*)bp;
            b1n = *(const float4*)(bp + 64);
        }
#pragma unroll
        for (int kk = 0; kk < TKK; kk++) {
            unsigned long long a8[8], b4[4];
#pragma unroll
            for (int i = 0; i < 4; i++) {
                ulonglong2 t2 = *(const ulonglong2*)&As[buf][kk][2 * (ty * 8 + 2 * i)];
                a8[2 * i] = t2.x;  a8[2 * i + 1] = t2.y;
            }
            {
                ulonglong2 t0 = *(const ulonglong2*)&Bs[buf][kk][4 * tx];
                ulonglong2 t1 = *(const ulonglong2*)&Bs[buf][kk][64 + 4 * tx];
                b4[0] = t0.x;  b4[1] = t0.y;  b4[2] = t1.x;  b4[3] = t1.y;
            }
            // i-outer/j-inner: measured-best schedule (R9/R10)
#pragma unroll
            for (int i = 0; i < 8; i++)
#pragma unroll
                for (int j = 0; j < 4; j++) ffma2(acc[i][j], a8[i], b4[j]);
        }
        if (more) {
            int nb = buf ^ 1;
#pragma unroll
            for (int j = 0; j < 4; j++) {
                float v0 = (&a0n.x)[j], v1 = (&a1n.x)[j];
                *(float2*)&As[nb][ak + j][2 * ar] = make_float2(v0, v0);
                *(float2*)&As[nb][ak + 4 + j][2 * ar] = make_float2(v1, v1);
            }
            *(float4*)&Bs[nb][bk][4 * btx] = b0n;
            *(float4*)&Bs[nb][bk][64 + 4 * btx] = b1n;
            __syncthreads();
        }
    }

    // epilogue
#pragma unroll
    for (int i = 0; i < 8; i++) {
        int row = row0 + ty * 8 + i;
        float2 p0 = *(float2*)&acc[i][0];
        float2 p1 = *(float2*)&acc[i][1];
        float2 p2 = *(float2*)&acc[i][2];
        float2 p3 = *(float2*)&acc[i][3];
        if (COMBINE) {
            int tok = g_perm_tok[row];
            if (tok < 0) continue;
            float p = g_rowp[row];
            float* dst = Out + (size_t)tok * NO + bn0;
            red_add(dst + 4 * tx + 0, p * p0.x);
            red_add(dst + 4 * tx + 1, p * p0.y);
            red_add(dst + 4 * tx + 2, p * p1.x);
            red_add(dst + 4 * tx + 3, p * p1.y);
            red_add(dst + 64 + 4 * tx + 0, p * p2.x);
            red_add(dst + 64 + 4 * tx + 1, p * p2.y);
            red_add(dst + 64 + 4 * tx + 2, p * p3.x);
            red_add(dst + 64 + 4 * tx + 3, p * p3.y);
        } else {
            float* dst = Out + (size_t)row * NO + bn0;
            float4 v0, v1;
            if (RELU) {
                v0 = make_float4(fmaxf(p0.x, 0.f), fmaxf(p0.y, 0.f),
                                 fmaxf(p1.x, 0.f), fmaxf(p1.y, 0.f));
                v1 = make_float4(fmaxf(p2.x, 0.f), fmaxf(p2.y, 0.f),
                                 fmaxf(p3.x, 0.f), fmaxf(p3.y, 0.f));
            } else {
                v0 = make_float4(p0.x, p0.y, p1.x, p1.y);
                v1 = make_float4(p2.x, p2.y, p3.x, p3.y);
            }
            *(float4*)(dst + 4 * tx) = v0;
            *(float4*)(dst + 64 + 4 * tx) = v1;
        }
    }
}

// ---------------- fused persistent GEMM, distance-DELAY pipelined queue ----------------
// Virtual group g: slots r<16 -> G1 tiles of row g; slots r>=16 -> G2 tiles of row g-DELAY.
// G2 of row y is dispensed 576 tile-slots after y's last G1 tile -> no spin bubbles,
// while hidden row-tiles stay L2-resident between produce and consume (~25 MB window).
__global__ void __launch_bounds__(256, 2) moe_fused_gemm(
    const float* __restrict__ x, const float* __restrict__ w1,
    const float* __restrict__ w2, float* __restrict__ out)
{
    __shared__ float As[2][TKK][2 * TM];   // 32 KB
    __shared__ float Bs[2][TKK][TN];       // 16 KB
    __shared__ int s_t;
    int tid = threadIdx.x;
    int rows_used = g_off[NEXP];

    while (true) {
        __syncthreads();                       // smem reuse + s_t protection
        if (tid == 0) s_t = atomicAdd(&g_tile_ctr, 1);
        __syncthreads();
        int t = s_t;
        if (t >= TOT_TILES) return;

        int g = t / GRP, r = t % GRP;
        if (r < 16) {
            // GEMM1 tile of row g
            if (g >= NROWT) continue;
            int row0 = g * TM;
            if (row0 < rows_used)
                gemm_tile<true, true, false, DMODEL, HID>(x, w1, g_hidden, row0, r * TN, As, Bs);
            __threadfence();
            __syncthreads();
            if (tid == 0) atomicAdd(&g_ready[g], 1);
        } else {
            // GEMM2 tile of row g - DELAY
            int y = g - DELAY;
            if (y < 0 || y >= NROWT) continue;
            int row0 = y * TM;
            if (row0 >= rows_used) continue;
            if (tid == 0) {
                while (ld_acquire(&g_ready[y]) < 16) __nanosleep(64);
            }
            __syncthreads();
            gemm_tile<false, false, true, HID, DMODEL>(g_hidden, w2, out, row0, (r - 16) * TN, As, Bs);
        }
    }
}

// ---------------- aux loss ----------------
__global__ void aux_kernel(float* __restrict__ out, int out_size) {
    __shared__ float P[NEXP];
    int e = threadIdx.x;
    if (e < NEXP) {
        float s = 0.f;
        for (int b = 0; b < NTOK / 8; b++) s += g_blockP[b * NEXP + e];
        P[e] = s * (1.0f / NTOK);
    }
    __syncthreads();
    if (threadIdx.x == 0 && out_size > OUT_ELEMS) {
        float aux = 0.f;
        for (int q = 0; q < NEXP; q++)
            aux += ((float)g_fcount[q] * (1.0f / NTOK)) * P[q];
        aux *= 0.01f * NEXP;
        out[OUT_ELEMS] = aux;
    }
}

// ---------------- launch ----------------
extern "C" void kernel_launch(void* const* d_in, const int* in_sizes, int n_in,
                              void* d_out, int out_size) {
    const float* x      = (const float*)d_in[0];
    const float* gate_w = (const float*)d_in[1];
    const float* w1     = (const float*)d_in[2];
    const float* w2     = (const float*)d_in[3];
    float* out = (float*)d_out;

    cudaMemsetAsync(out, 0, (size_t)out_size * sizeof(float));
    prep_kernel<<<1, 256>>>();
    router_kernel<<<NTOK / 8, 256>>>(x, gate_w);
    offsets_kernel<<<1, 256>>>();
    scatter_kernel<<<(NTOK + 255) / 256, 256>>>();

    moe_fused_gemm<<<PERSIST_CTAS, 256>>>(x, w1, w2, out);

    aux_kernel<<<1, 32>>>(out, out_size);
}

// round 17
// speedup vs baseline: 1.2423x; 1.0244x over previous
#include <cuda_runtime.h>
#include <cstdint>

// Problem constants
#define NTOK   8192        // B*S = 4*2048
#define DMODEL 1024
#define NEXP   8
#define HID    2048
#define TOPK   2
#define TM     128
#define TN     128
#define TKK    16
#define MAXR   (NTOK*TOPK + NEXP*TM)   // 17408
#define NROWT  (MAXR/TM)               // 136 row tiles
#define T1_TILES ((HID/TN) * NROWT)    // 2176
#define T2_TILES ((DMODEL/TN) * NROWT) // 1088
#define OUT_ELEMS (NTOK*DMODEL)
#define PERSIST_CTAS 304               // 152 SM * 2

// ---------------- device scratch (no allocation allowed) ----------------
__device__ int   g_tope[NTOK*2];
__device__ float g_topp[NTOK*2];
__device__ int   g_perm_tok[MAXR];
__device__ float g_rowp[MAXR];          // per permuted row: gating prob
__device__ int   g_fcount[NEXP];
__device__ int   g_scount[NEXP];
__device__ int   g_off[NEXP+1];
__device__ int   g_cursor[NEXP];
__device__ float g_blockP[(NTOK/8)*NEXP];
__device__ int   g_tile_ctr;
__device__ int   g_ready[NROWT];
__device__ float g_hidden[(size_t)MAXR*HID];

// ---------------- prep: zero the small control state (1 block) ----------------
__global__ void prep_kernel() {
    int i = threadIdx.x;
    if (i < NEXP) { g_fcount[i] = 0; g_scount[i] = 0; }
    if (i < NROWT) g_ready[i] = 0;
    if (i == 0) g_tile_ctr = 0;
}

// ---------------- router ----------------
__global__ void __launch_bounds__(256) router_kernel(const float* __restrict__ x,
                                                     const float* __restrict__ gate_w) {
    __shared__ float sg[NEXP * DMODEL];
    __shared__ float warpP[8][NEXP];
    int tid = threadIdx.x;
    for (int i = tid; i < NEXP * DMODEL; i += 256) sg[i] = gate_w[i];
    __syncthreads();

    int warp = tid >> 5, lane = tid & 31;
    int t = blockIdx.x * 8 + warp;
    const float* xr = x + (size_t)t * DMODEL;

    float acc[NEXP];
#pragma unroll
    for (int e = 0; e < NEXP; e++) acc[e] = 0.f;
    for (int j = 0; j < DMODEL / 32; j++) {
        float v = xr[j * 32 + lane];
#pragma unroll
        for (int e = 0; e < NEXP; e++) acc[e] += v * sg[e * DMODEL + j * 32 + lane];
    }
#pragma unroll
    for (int e = 0; e < NEXP; e++)
#pragma unroll
        for (int o = 16; o > 0; o >>= 1) acc[e] += __shfl_xor_sync(0xffffffffu, acc[e], o);

    if (lane == 0) {
        float m = acc[0];
#pragma unroll
        for (int e = 1; e < NEXP; e++) m = fmaxf(m, acc[e]);
        float p[NEXP], s = 0.f;
#pragma unroll
        for (int e = 0; e < NEXP; e++) { p[e] = __expf(acc[e] - m); s += p[e]; }
        float inv = 1.f / s;
#pragma unroll
        for (int e = 0; e < NEXP; e++) p[e] *= inv;
        int i1 = 0;
#pragma unroll
        for (int e = 1; e < NEXP; e++) if (p[e] > p[i1]) i1 = e;
        int i2 = (i1 == 0) ? 1 : 0;
#pragma unroll
        for (int e = 0; e < NEXP; e++) if (e != i1 && p[e] > p[i2]) i2 = e;
        float s2 = p[i1] + p[i2];
        g_tope[t * 2 + 0] = i1;  g_topp[t * 2 + 0] = p[i1] / s2;
        g_tope[t * 2 + 1] = i2;  g_topp[t * 2 + 1] = p[i2] / s2;
        atomicAdd(&g_fcount[i1], 1);
        atomicAdd(&g_scount[i1], 1);
        atomicAdd(&g_scount[i2], 1);
#pragma unroll
        for (int e = 0; e < NEXP; e++) warpP[warp][e] = p[e];
    }
    __syncthreads();
    if (tid < NEXP) {
        float s = 0.f;
#pragma unroll
        for (int w = 0; w < 8; w++) s += warpP[w][tid];
        g_blockP[blockIdx.x * NEXP + tid] = s;
    }
}

// ---------------- offsets + padding fill ----------------
__global__ void __launch_bounds__(256) offsets_kernel() {
    __shared__ int soff[NEXP + 1];
    __shared__ int scnt[NEXP];
    if (threadIdx.x == 0) {
        int o = 0;
        for (int e = 0; e < NEXP; e++) {
            g_off[e] = o; soff[e] = o;
            g_cursor[e] = o;
            int c = g_scount[e];
            scnt[e] = c;
            o += ((c + TM - 1) / TM) * TM;
        }
        g_off[NEXP] = o; soff[NEXP] = o;
    }
    __syncthreads();
    // fill padding rows with -1
    for (int e = 0; e < NEXP; e++) {
        int start = soff[e] + scnt[e], end = soff[e + 1];
        for (int i = start + threadIdx.x; i < end; i += 256) g_perm_tok[i] = -1;
    }
}

// ---------------- scatter ----------------
__global__ void scatter_kernel() {
    int t = blockIdx.x * blockDim.x + threadIdx.x;
    if (t >= NTOK) return;
#pragma unroll
    for (int k = 0; k < 2; k++) {
        int e = g_tope[t * 2 + k];
        int pos = atomicAdd(&g_cursor[e], 1);
        g_perm_tok[pos] = t;
        g_rowp[pos] = g_topp[t * 2 + k];
    }
}

// ---------------- helpers ----------------
__device__ __forceinline__ void ffma2(unsigned long long& c, unsigned long long a,
                                      unsigned long long b) {
    asm("fma.rn.f32x2 %0, %1, %2, %0;" : "+l"(c) : "l"(a), "l"(b));
}
__device__ __forceinline__ int ld_acquire(const int* p) {
    int v;
    asm volatile("ld.acquire.gpu.s32 %0, [%1];" : "=r"(v) : "l"(p) : "memory");
    return v;
}
__device__ __forceinline__ void red_add(float* p, float v) {
    asm volatile("red.global.add.f32 [%0], %1;" :: "l"(p), "f"(v) : "memory");
}

// ---------------- one 128x128 GEMM tile (R10 proven mapping + loop order) ----------------
// COMBINE=false: store to Out (optionally relu). COMBINE=true: atomic-scatter to out.
template<bool GATHER, bool RELU, bool COMBINE, int KD, int NO>
__device__ __forceinline__ void gemm_tile(
    const float* __restrict__ Asrc, const float* __restrict__ W,
    float* __restrict__ Out, int row0, int bn0,
    float (*As)[TKK][2 * TM], float (*Bs)[TKK][TN])
{
    int e = 0;
#pragma unroll
    for (int q = 1; q < NEXP; q++) if (row0 >= g_off[q]) e = q;
    const float* B = W + (size_t)e * KD * NO;
    int tid = threadIdx.x;

    int ar = tid >> 1, ak = (tid & 1) * 8;
    int bk = tid >> 4, btx = tid & 15;
    int tx = tid & 15, ty = tid >> 4;
    int tokA = 0;
    const float* Arow;
    if (GATHER) {
        tokA = g_perm_tok[row0 + ar];
        Arow = (tokA >= 0) ? (Asrc + (size_t)tokA * KD + ak) : Asrc;
    } else {
        Arow = Asrc + (size_t)(row0 + ar) * KD + ak;
    }
    const float* Brow = B + (size_t)bk * NO + bn0 + 4 * btx;

    unsigned long long acc[8][4];
#pragma unroll
    for (int i = 0; i < 8; i++)
#pragma unroll
        for (int j = 0; j < 4; j++) acc[i][j] = 0ull;

    // prologue: tile 0
    {
        float4 a0 = make_float4(0.f, 0.f, 0.f, 0.f), a1 = a0;
        if (!GATHER || tokA >= 0) { a0 = *(const float4*)(Arow); a1 = *(const float4*)(Arow + 4); }
#pragma unroll
        for (int j = 0; j < 4; j++) {
            float v0 = (&a0.x)[j], v1 = (&a1.x)[j];
            *(float2*)&As[0][ak + j][2 * ar] = make_float2(v0, v0);
            *(float2*)&As[0][ak + 4 + j][2 * ar] = make_float2(v1, v1);
        }
        *(float4*)&Bs[0][bk][4 * btx] = *(const float4*)Brow;
        *(float4*)&Bs[0][bk][64 + 4 * btx] = *(const float4*)(Brow + 64);
    }
    __syncthreads();

    const int nk = KD / TKK;
    for (int kt = 0; kt < nk; kt++) {
        int buf = kt & 1;
        float4 a0n, a1n, b0n, b1n;
        bool more = (kt + 1 < nk);
        if (more) {
            a0n = make_float4(0.f, 0.f, 0.f, 0.f); a1n = a0n;
            if (!GATHER || tokA >= 0) {
                a0n = *(const float4*)(Arow + (kt + 1) * TKK);
                a1n = *(const float4*)(Arow + (kt + 1) * TKK + 4);
            }
            const float* bp = Brow + (size_t)(kt + 1) * TKK * NO;
            b0n = *(const float4*)bp;
            b1n = *(const float4*)(bp + 64);
        }
#pragma unroll
        for (int kk = 0; kk < TKK; kk++) {
            unsigned long long a8[8], b4[4];
#pragma unroll
            for (int i = 0; i < 4; i++) {
                ulonglong2 t2 = *(const ulonglong2*)&As[buf][kk][2 * (ty * 8 + 2 * i)];
                a8[2 * i] = t2.x;  a8[2 * i + 1] = t2.y;
            }
            {
                ulonglong2 t0 = *(const ulonglong2*)&Bs[buf][kk][4 * tx];
                ulonglong2 t1 = *(const ulonglong2*)&Bs[buf][kk][64 + 4 * tx];
                b4[0] = t0.x;  b4[1] = t0.y;  b4[2] = t1.x;  b4[3] = t1.y;
            }
            // i-outer/j-inner: measured-best schedule (R9/R10)
#pragma unroll
            for (int i = 0; i < 8; i++)
#pragma unroll
                for (int j = 0; j < 4; j++) ffma2(acc[i][j], a8[i], b4[j]);
        }
        if (more) {
            int nb = buf ^ 1;
#pragma unroll
            for (int j = 0; j < 4; j++) {
                float v0 = (&a0n.x)[j], v1 = (&a1n.x)[j];
                *(float2*)&As[nb][ak + j][2 * ar] = make_float2(v0, v0);
                *(float2*)&As[nb][ak + 4 + j][2 * ar] = make_float2(v1, v1);
            }
            *(float4*)&Bs[nb][bk][4 * btx] = b0n;
            *(float4*)&Bs[nb][bk][64 + 4 * btx] = b1n;
            __syncthreads();
        }
    }

    // epilogue
#pragma unroll
    for (int i = 0; i < 8; i++) {
        int row = row0 + ty * 8 + i;
        float2 p0 = *(float2*)&acc[i][0];
        float2 p1 = *(float2*)&acc[i][1];
        float2 p2 = *(float2*)&acc[i][2];
        float2 p3 = *(float2*)&acc[i][3];
        if (COMBINE) {
            int tok = g_perm_tok[row];
            if (tok < 0) continue;
            float p = g_rowp[row];
            float* dst = Out + (size_t)tok * NO + bn0;
            red_add(dst + 4 * tx + 0, p * p0.x);
            red_add(dst + 4 * tx + 1, p * p0.y);
            red_add(dst + 4 * tx + 2, p * p1.x);
            red_add(dst + 4 * tx + 3, p * p1.y);
            red_add(dst + 64 + 4 * tx + 0, p * p2.x);
            red_add(dst + 64 + 4 * tx + 1, p * p2.y);
            red_add(dst + 64 + 4 * tx + 2, p * p3.x);
            red_add(dst + 64 + 4 * tx + 3, p * p3.y);
        } else {
            float* dst = Out + (size_t)row * NO + bn0;
            float4 v0, v1;
            if (RELU) {
                v0 = make_float4(fmaxf(p0.x, 0.f), fmaxf(p0.y, 0.f),
                                 fmaxf(p1.x, 0.f), fmaxf(p1.y, 0.f));
                v1 = make_float4(fmaxf(p2.x, 0.f), fmaxf(p2.y, 0.f),
                                 fmaxf(p3.x, 0.f), fmaxf(p3.y, 0.f));
            } else {
                v0 = make_float4(p0.x, p0.y, p1.x, p1.y);
                v1 = make_float4(p2.x, p2.y, p3.x, p3.y);
            }
            *(float4*)(dst + 4 * tx) = v0;
            *(float4*)(dst + 64 + 4 * tx) = v1;
        }
    }
}

// ---------------- fused persistent GEMM1+GEMM2(+combine) with tile queue (R14 order) ----------------
__global__ void __launch_bounds__(256, 2) moe_fused_gemm(
    const float* __restrict__ x, const float* __restrict__ w1,
    const float* __restrict__ w2, float* __restrict__ out)
{
    __shared__ float As[2][TKK][2 * TM];   // 32 KB
    __shared__ float Bs[2][TKK][TN];       // 16 KB
    __shared__ int s_t;
    int tid = threadIdx.x;
    int rows_used = g_off[NEXP];

    while (true) {
        __syncthreads();                       // smem reuse + s_t protection
        if (tid == 0) s_t = atomicAdd(&g_tile_ctr, 1);
        __syncthreads();
        int t = s_t;
        if (t >= T1_TILES + T2_TILES) return;

        if (t < T1_TILES) {
            int y = t >> 4, xblk = t & 15;
            int row0 = y * TM;
            if (row0 < rows_used)
                gemm_tile<true, true, false, DMODEL, HID>(x, w1, g_hidden, row0, xblk * TN, As, Bs);
            __threadfence();
            __syncthreads();
            if (tid == 0) atomicAdd(&g_ready[y], 1);
        } else {
            int idx = t - T1_TILES;
            int y = idx >> 3, xblk = idx & 7;
            int row0 = y * TM;
            if (row0 >= rows_used) continue;
            if (tid == 0) {
                while (ld_acquire(&g_ready[y]) < 16) __nanosleep(64);
            }
            __syncthreads();
            gemm_tile<false, false, true, HID, DMODEL>(g_hidden, w2, out, row0, xblk * TN, As, Bs);
        }
    }
}

// ---------------- aux loss ----------------
__global__ void aux_kernel(float* __restrict__ out, int out_size) {
    __shared__ float P[NEXP];
    int e = threadIdx.x;
    if (e < NEXP) {
        float s = 0.f;
        for (int b = 0; b < NTOK / 8; b++) s += g_blockP[b * NEXP + e];
        P[e] = s * (1.0f / NTOK);
    }
    __syncthreads();
    if (threadIdx.x == 0 && out_size > OUT_ELEMS) {
        float aux = 0.f;
        for (int q = 0; q < NEXP; q++)
            aux += ((float)g_fcount[q] * (1.0f / NTOK)) * P[q];
        aux *= 0.01f * NEXP;
        out[OUT_ELEMS] = aux;
    }
}

// ---------------- launch ----------------
extern "C" void kernel_launch(void* const* d_in, const int* in_sizes, int n_in,
                              void* d_out, int out_size) {
    const float* x      = (const float*)d_in[0];
    const float* gate_w = (const float*)d_in[1];
    const float* w1     = (const float*)d_in[2];
    const float* w2     = (const float*)d_in[3];
    float* out = (float*)d_out;

    cudaMemsetAsync(out, 0, (size_t)out_size * sizeof(float));
    prep_kernel<<<1, 256>>>();
    router_kernel<<<NTOK / 8, 256>>>(x, gate_w);
    offsets_kernel<<<1, 256>>>();
    scatter_kernel<<<(NTOK + 255) / 256, 256>>>();

    // aux depends only on router outputs; launch it before the long GEMM so its
    // latency hides instead of trailing the critical path.
    aux_kernel<<<1, 32>>>(out, out_size);

    moe_fused_gemm<<<PERSIST_CTAS, 256>>>(x, w1, w2, out);
}